// round 15
// baseline (speedup 1.0000x reference)
#include <cuda_runtime.h>

// ---------------------------------------------------------------------------
// ImprovedAILayerNorm: int8-quantized layernorm with LUT integer sqrt.
// R15 = R14 with the k_quant-winning memory shape (256 thr/block, 1 row,
// 4 independent float4 loads in flight) applied to BOTH reduction passes.
// PDL chain + serpentine (p1 asc, p2 desc, p3 asc) + stcs output kept.
// ---------------------------------------------------------------------------

#define T3 256
#define NW3 (T3 / 32)
#define MAX_ROWS 32768

__device__ int   g_absmax_bits;
__device__ int   g_ymax_bits;
__device__ int   g_const_flag;
__device__ float g_g0, g_b0;
__device__ float g_mu[MAX_ROWS];
__device__ float g_inv_std[MAX_ROWS];
__device__ float g_rowmin[MAX_ROWS];
__device__ float g_rowmax[MAX_ROWS];

__device__ __forceinline__ void pdl_launch_dependents() {
    asm volatile("griddepcontrol.launch_dependents;" ::: "memory");
}
__device__ __forceinline__ void pdl_wait() {
    asm volatile("griddepcontrol.wait;" ::: "memory");
}

// ---------------------------------------------------------------------------
__global__ void k_init_check(const float* __restrict__ gamma,
                             const float* __restrict__ beta, int N) {
    pdl_launch_dependents();
    if (threadIdx.x == 0) {
        g_absmax_bits = 0;
        g_ymax_bits   = 0;
        g_const_flag  = 1;
        g_g0 = gamma[0];
        g_b0 = beta[0];
    }
    __syncthreads();
    float g0 = g_g0, b0 = g_b0;
    bool bad = false;
    for (int i = threadIdx.x; i < N; i += blockDim.x)
        bad |= (gamma[i] != g0) || (beta[i] != b0);
    if (__syncthreads_or(bad) && threadIdx.x == 0) g_const_flag = 0;
}

// ordered-uint mapping for float min/max redux
__device__ __forceinline__ unsigned f2ord(float f) {
    unsigned u = __float_as_uint(f);
    return (u & 0x80000000u) ? ~u : (u | 0x80000000u);
}
__device__ __forceinline__ float ord2f(unsigned u) {
    return __uint_as_float((u & 0x80000000u) ? (u & 0x7fffffffu) : ~u);
}
__device__ __forceinline__ float v4min(float4 v) {
    return fminf(fminf(v.x, v.y), fminf(v.z, v.w));
}
__device__ __forceinline__ float v4max(float4 v) {
    return fmaxf(fmaxf(v.x, v.y), fmaxf(v.z, v.w));
}

// ---------------------------------------------------------------------------
// Pass 1: 1 row/block, 256 thr, 4 independent float4 loads. ASCENDING rows.
__global__ void __launch_bounds__(T3)
k_minmax(const float* __restrict__ x, int N) {
    pdl_launch_dependents();
    const int row = blockIdx.x;
    const float4* xr = reinterpret_cast<const float4*>(x + (size_t)row * N);

    float4 v0 = xr[threadIdx.x];
    float4 v1 = xr[T3 + threadIdx.x];
    float4 v2 = xr[2 * T3 + threadIdx.x];
    float4 v3 = xr[3 * T3 + threadIdx.x];

    float mn = fminf(fminf(v4min(v0), v4min(v1)), fminf(v4min(v2), v4min(v3)));
    float mx = fmaxf(fmaxf(v4max(v0), v4max(v1)), fmaxf(v4max(v2), v4max(v3)));

    unsigned wmn = __reduce_min_sync(0xffffffffu, f2ord(mn));
    unsigned wmx = __reduce_max_sync(0xffffffffu, f2ord(mx));

    __shared__ unsigned smn[NW3], smx[NW3];
    const int w = threadIdx.x >> 5;
    if ((threadIdx.x & 31) == 0) { smn[w] = wmn; smx[w] = wmx; }
    __syncthreads();
    if (threadIdx.x == 0) {
        unsigned umn = smn[0], umx = smx[0];
        #pragma unroll
        for (int i = 1; i < NW3; i++) {
            umn = min(umn, smn[i]);
            umx = max(umx, smx[i]);
        }
        float fmn = ord2f(umn), fmx = ord2f(umx);
        g_rowmin[row] = fmn;
        g_rowmax[row] = fmx;
        float am = fmaxf(fabsf(fmn), fabsf(fmx));
        pdl_wait();                              // init's zeroing visible
        atomicMax(&g_absmax_bits, (int)__float_as_uint(am));
    }
}

// ---------------------------------------------------------------------------
// Exact replica of reference sqrt_rounded_vec (LUT-based rounded int sqrt)
__device__ __forceinline__ float sqrt_rounded(int d) {
    int msb = 31 - __clz(d);
    int k   = msb >> 1;
    int dn  = d << ((7 - k) * 2);
    int addr = (dn >> 8) & 255;
    int v    = addr * 256 + 128;
    int mant = (int)sqrtf((float)v);
    if (mant * mant > v) mant--;
    if ((mant + 1) * (mant + 1) <= v) mant++;
    int qf = mant >> (7 - k);
    int boundary = qf * qf + qf;
    return (float)((d > boundary) ? qf + 1 : qf);
}

// ---------------------------------------------------------------------------
// Pass 2: 1 row/block, 256 thr, 4 independent float4 loads. DESCENDING.
// No clamps (|x|/s <= 127 by construction of s). x preloaded pre-wait.
__global__ void __launch_bounds__(T3)
k_rowstats(const float* __restrict__ x,
           const float* __restrict__ gamma,
           const float* __restrict__ beta,
           int N, int rows) {
    pdl_launch_dependents();
    const int row = rows - 1 - blockIdx.x;             // descending
    const float4* xr = reinterpret_cast<const float4*>(x + (size_t)row * N);

    float4 v0 = xr[threadIdx.x];
    float4 v1 = xr[T3 + threadIdx.x];
    float4 v2 = xr[2 * T3 + threadIdx.x];
    float4 v3 = xr[3 * T3 + threadIdx.x];

    pdl_wait();                                        // absmax/flag final
    const bool cst = (g_const_flag != 0);
    const float s     = fmaxf(__int_as_float(g_absmax_bits) / 127.0f, 1e-8f);
    const float inv_s = 1.0f / s;

    int su = 0, su2 = 0;
    #pragma unroll
    for (int c = 0; c < 4; c++) {
        int q0 = __float2int_rn((&v0.x)[c] * inv_s);   // RN half-even
        int q1 = __float2int_rn((&v1.x)[c] * inv_s);
        int q2 = __float2int_rn((&v2.x)[c] * inv_s);
        int q3 = __float2int_rn((&v3.x)[c] * inv_s);
        su  += q0 + q1 + q2 + q3;
        su2 += q0 * q0 + q1 * q1 + q2 * q2 + q3 * q3;
    }
    su  = __reduce_add_sync(0xffffffffu, su);
    su2 = __reduce_add_sync(0xffffffffu, su2);

    __shared__ int sw[2][NW3];
    __shared__ float s_mu, s_is;
    const int w = threadIdx.x >> 5;
    if ((threadIdx.x & 31) == 0) { sw[0][w] = su; sw[1][w] = su2; }
    __syncthreads();
    if (threadIdx.x == 0) {
        int t = 0, t2 = 0;
        #pragma unroll
        for (int i = 0; i < NW3; i++) { t += sw[0][i]; t2 += sw[1][i]; }
        float Ex  = (float)t  * s;
        float Ex2 = (float)t2 * (s * s);
        float mu  = Ex / (float)N;
        float var = fmaxf(Ex2 / (float)N - mu * mu, 0.0f);
        float vi  = fminf(fmaxf(rintf(var), 1.0f), 65535.0f);
        float inv = 1.0f / fmaxf(sqrt_rounded((int)vi), 1e-5f);
        g_mu[row] = mu;
        g_inv_std[row] = inv;
        if (cst) {
            float g0 = g_g0, b0 = g_b0;
            float y1 = fabsf((g_rowmax[row] - mu) * inv * g0 + b0);
            float y2 = fabsf((g_rowmin[row] - mu) * inv * g0 + b0);
            atomicMax(&g_ymax_bits, (int)__float_as_uint(fmaxf(y1, y2)));
        } else {
            s_mu = mu; s_is = inv;
        }
    }
    if (cst) return;

    // ---- general gamma/beta path: sweep row for max|y| ----
    __syncthreads();
    const float mu = s_mu, is = s_is;
    const float4* g4 = reinterpret_cast<const float4*>(gamma);
    const float4* b4 = reinterpret_cast<const float4*>(beta);
    float ymax = 0.0f;
    #pragma unroll
    for (int j = 0; j < 4; j++) {
        float4 v = (j == 0) ? v0 : (j == 1) ? v1 : (j == 2) ? v2 : v3;
        float4 g = g4[j * T3 + threadIdx.x];
        float4 b = b4[j * T3 + threadIdx.x];
        #pragma unroll
        for (int c = 0; c < 4; c++) {
            float y = ((&v.x)[c] - mu) * is * (&g.x)[c] + (&b.x)[c];
            ymax = fmaxf(ymax, fabsf(y));
        }
    }
    unsigned yb = __reduce_max_sync(0xffffffffu, __float_as_uint(ymax));
    __shared__ unsigned sy[NW3];
    if ((threadIdx.x & 31) == 0) sy[w] = yb;
    __syncthreads();
    if (threadIdx.x == 0) {
        unsigned v = 0;
        #pragma unroll
        for (int i = 0; i < NW3; i++) v = max(v, sy[i]);
        atomicMax(&g_ymax_bits, (int)v);
    }
}

// ---------------------------------------------------------------------------
// Pass 3: 1 row/block, 256 thr, 4 independent __ldcs float4 loads (MLP=4).
// ASCENDING rows; out streamed with __stcs. (Unchanged from R14.)
__global__ void __launch_bounds__(T3)
k_quant(const float* __restrict__ x,
        const float* __restrict__ gamma,
        const float* __restrict__ beta,
        float* __restrict__ out,
        int N) {
    const int row = blockIdx.x;
    const float4* xr = reinterpret_cast<const float4*>(x + (size_t)row * N);
    float4* orow = reinterpret_cast<float4*>(out + (size_t)row * N);

    float4 v0 = __ldcs(&xr[threadIdx.x]);
    float4 v1 = __ldcs(&xr[T3 + threadIdx.x]);
    float4 v2 = __ldcs(&xr[2 * T3 + threadIdx.x]);
    float4 v3 = __ldcs(&xr[3 * T3 + threadIdx.x]);

    pdl_wait();                                        // mu/inv_std/ymax final
    const float mu = g_mu[row];
    const float is = g_inv_std[row];
    const float so     = fmaxf(__int_as_float(g_ymax_bits) / 127.0f, 1e-8f);
    const float inv_so = 1.0f / so;

    if (g_const_flag) {
        const float g0 = g_g0, b0 = g_b0;
        const float A2 = is * g0 * inv_so;
        const float B2 = (b0 - mu * is * g0) * inv_so;
        float4 o0, o1, o2, o3;
        #pragma unroll
        for (int c = 0; c < 4; c++) {
            int q0 = __float2int_rn(fmaf((&v0.x)[c], A2, B2));
            int q1 = __float2int_rn(fmaf((&v1.x)[c], A2, B2));
            int q2 = __float2int_rn(fmaf((&v2.x)[c], A2, B2));
            int q3 = __float2int_rn(fmaf((&v3.x)[c], A2, B2));
            q0 = max(-127, min(127, q0));              // safety vs reassoc ulp
            q1 = max(-127, min(127, q1));
            q2 = max(-127, min(127, q2));
            q3 = max(-127, min(127, q3));
            (&o0.x)[c] = (float)q0 * so;
            (&o1.x)[c] = (float)q1 * so;
            (&o2.x)[c] = (float)q2 * so;
            (&o3.x)[c] = (float)q3 * so;
        }
        __stcs(&orow[threadIdx.x], o0);
        __stcs(&orow[T3 + threadIdx.x], o1);
        __stcs(&orow[2 * T3 + threadIdx.x], o2);
        __stcs(&orow[3 * T3 + threadIdx.x], o3);
        return;
    }

    const float4* g4 = reinterpret_cast<const float4*>(gamma);
    const float4* b4 = reinterpret_cast<const float4*>(beta);
    #pragma unroll
    for (int j = 0; j < 4; j++) {
        float4 v = (j == 0) ? v0 : (j == 1) ? v1 : (j == 2) ? v2 : v3;
        float4 g = g4[j * T3 + threadIdx.x];
        float4 b = b4[j * T3 + threadIdx.x];
        float4 o;
        #pragma unroll
        for (int c = 0; c < 4; c++) {
            float y = ((&v.x)[c] - mu) * is * (&g.x)[c] + (&b.x)[c];
            (&o.x)[c] = (float)__float2int_rn(y * inv_so) * so;
        }
        __stcs(&orow[j * T3 + threadIdx.x], o);
    }
}

// ---------------------------------------------------------------------------
static void launch_pdl(void* func, dim3 grid, dim3 block, void** args) {
    cudaLaunchConfig_t cfg = {};
    cfg.gridDim = grid;
    cfg.blockDim = block;
    cfg.stream = 0;
    cudaLaunchAttribute attr[1];
    attr[0].id = cudaLaunchAttributeProgrammaticStreamSerialization;
    attr[0].val.programmaticStreamSerializationAllowed = 1;
    cfg.attrs = attr;
    cfg.numAttrs = 1;
    cudaLaunchKernelExC(&cfg, func, args);
}

extern "C" void kernel_launch(void* const* d_in, const int* in_sizes, int n_in,
                              void* d_out, int out_size) {
    const float* x     = (const float*)d_in[0];
    const float* gamma = (const float*)d_in[1];
    const float* beta  = (const float*)d_in[2];
    float* out = (float*)d_out;

    int N    = in_sizes[1];              // 4096
    const int n = in_sizes[0];           // 4*2048*4096
    int rows = n / N;                    // 8192

    {   // init+check (plain launch)
        void* args[] = {(void*)&gamma, (void*)&beta, (void*)&N};
        cudaLaunchConfig_t cfg = {};
        cfg.gridDim = dim3(1); cfg.blockDim = dim3(T3); cfg.stream = 0;
        cudaLaunchKernelExC(&cfg, (void*)k_init_check, args);
    }
    {   // pass 1 (PDL after init)
        void* args[] = {(void*)&x, (void*)&N};
        launch_pdl((void*)k_minmax, dim3(rows), dim3(T3), args);
    }
    {   // pass 2 (PDL after pass 1)
        void* args[] = {(void*)&x, (void*)&gamma, (void*)&beta,
                        (void*)&N, (void*)&rows};
        launch_pdl((void*)k_rowstats, dim3(rows), dim3(T3), args);
    }
    {   // pass 3 (PDL after pass 2)
        void* args[] = {(void*)&x, (void*)&gamma, (void*)&beta,
                        (void*)&out, (void*)&N};
        launch_pdl((void*)k_quant, dim3(rows), dim3(T3), args);
    }
}